// round 2
// baseline (speedup 1.0000x reference)
#include <cuda_runtime.h>
#include <cstdint>

// QORNN: B=256, T=1024, I=64, H=256, O=16
// Exact integer reformulation:
//   x_q  = clip(rint(x*128), -128, 127)           (int8, scale 1/128)
//   Wi_q = clip(rint(Wi*8), -8, 7)                (int4-valued int8, scale 1/8)
//   Wr_q, Wo_q likewise
//   z = (sum x_q*Wi_q + sum h_q*Wr_q) / 1024      (int32 accum, exact)
//   m = relu(|z| + b); h_q = clip(rint(sign(z)*m*128), -128, 127)
// All fp32 ops in the reference on these grids are exact, so int32 dp4a
// accumulation reproduces the reference bitwise (modrelu float ops identical).

#define TT 1024
#define NB 256
#define HH 256
#define NI 64
#define NO 16

__device__ uint32_t g_WiP[HH * 16];   // packed int8 x4, row-major per hidden unit
__device__ uint32_t g_WrP[HH * 64];
__device__ uint32_t g_WoP[NO * 64];

__device__ __forceinline__ int clampi(int v, int lo, int hi) {
    return v < lo ? lo : (v > hi ? hi : v);
}

__device__ __forceinline__ uint32_t pack4(const float* p, float scale, int lo, int hi) {
    uint32_t w = 0;
#pragma unroll
    for (int j = 0; j < 4; j++) {
        int q = clampi((int)rintf(p[j] * scale), lo, hi);
        w |= ((uint32_t)(uint8_t)(int8_t)q) << (8 * j);
    }
    return w;
}

__global__ void prep_kernel(const float* __restrict__ Wi,
                            const float* __restrict__ Wr,
                            const float* __restrict__ Wo) {
    int c = threadIdx.x;  // 0..255
    for (int kw = 0; kw < 64; kw++)
        g_WrP[c * 64 + kw] = pack4(Wr + c * HH + kw * 4, 8.0f, -8, 7);
    for (int kw = 0; kw < 16; kw++)
        g_WiP[c * 16 + kw] = pack4(Wi + c * NI + kw * 4, 8.0f, -8, 7);
    if (c < NO) {
        for (int kw = 0; kw < 64; kw++)
            g_WoP[c * 64 + kw] = pack4(Wo + c * HH + kw * 4, 8.0f, -8, 7);
    }
}

// One CTA = 2 batch rows for all T steps. Thread c owns output column c.
// Wr/Wi rows live in registers; h (int8) ping-pongs through SMEM.
__global__ __launch_bounds__(256, 1)
void qornn_kernel(const float* __restrict__ x,
                  const float* __restrict__ b,
                  float* __restrict__ out) {
    __shared__ uint32_t sh_h[2][2][64];   // [buf][row][kword] : 2 rows x 256 int8
    __shared__ uint32_t sh_x[2][2][16];   // [buf][row][kword] : 2 rows x 64 int8

    const int tid = threadIdx.x;
    const int r0 = blockIdx.x * 2;

    // Register-resident weights for this thread's output column
    uint32_t wr[64];
#pragma unroll
    for (int kw = 0; kw < 64; kw++) wr[kw] = g_WrP[tid * 64 + kw];
    uint32_t wi[16];
#pragma unroll
    for (int kw = 0; kw < 16; kw++) wi[kw] = g_WiP[tid * 16 + kw];
    const float bc = b[tid];

    // h0 = 0 (zero both buffers: 256 words total)
    ((uint32_t*)sh_h)[tid] = 0u;

    // Pre-quantize x for t=0 into sh_x buffer 0
    int pr = 0, pi = 0;
    if (tid < 128) {
        pr = tid >> 6;          // row within CTA
        pi = tid & 63;          // input feature
        float xv = x[(size_t)(r0 + pr) * (TT * NI) + pi];
        int q = clampi((int)rintf(xv * 128.0f), -128, 127);
        ((int8_t*)sh_x[0])[pr * 64 + pi] = (int8_t)q;
    }
    __syncthreads();

    for (int t = 0; t < TT; t++) {
        const int cur = t & 1;
        const int nxt = cur ^ 1;

        // Prefetch x(t+1) early; latency hidden under the dp4a block
        float xv = 0.0f;
        if (tid < 128) {
            int tn = (t + 1 < TT) ? (t + 1) : (TT - 1);
            xv = x[(size_t)(r0 + pr) * (TT * NI) + (size_t)tn * NI + pi];
        }

        int a0 = 0, a1 = 0;   // input-projection partials (rows 0,1)
        int c0 = 0, c1 = 0;   // recurrent partials

        const uint4* x0 = (const uint4*)sh_x[cur][0];
        const uint4* x1 = (const uint4*)sh_x[cur][1];
#pragma unroll
        for (int k = 0; k < 4; k++) {
            uint4 v0 = x0[k], v1 = x1[k];
            a0 = __dp4a((int)v0.x, (int)wi[4 * k + 0], a0);
            a0 = __dp4a((int)v0.y, (int)wi[4 * k + 1], a0);
            a0 = __dp4a((int)v0.z, (int)wi[4 * k + 2], a0);
            a0 = __dp4a((int)v0.w, (int)wi[4 * k + 3], a0);
            a1 = __dp4a((int)v1.x, (int)wi[4 * k + 0], a1);
            a1 = __dp4a((int)v1.y, (int)wi[4 * k + 1], a1);
            a1 = __dp4a((int)v1.z, (int)wi[4 * k + 2], a1);
            a1 = __dp4a((int)v1.w, (int)wi[4 * k + 3], a1);
        }

        const uint4* h0 = (const uint4*)sh_h[cur][0];
        const uint4* h1 = (const uint4*)sh_h[cur][1];
#pragma unroll
        for (int k = 0; k < 16; k++) {
            uint4 v0 = h0[k], v1 = h1[k];
            c0 = __dp4a((int)v0.x, (int)wr[4 * k + 0], c0);
            c0 = __dp4a((int)v0.y, (int)wr[4 * k + 1], c0);
            c0 = __dp4a((int)v0.z, (int)wr[4 * k + 2], c0);
            c0 = __dp4a((int)v0.w, (int)wr[4 * k + 3], c0);
            c1 = __dp4a((int)v1.x, (int)wr[4 * k + 0], c1);
            c1 = __dp4a((int)v1.y, (int)wr[4 * k + 1], c1);
            c1 = __dp4a((int)v1.z, (int)wr[4 * k + 2], c1);
            c1 = __dp4a((int)v1.w, (int)wr[4 * k + 3], c1);
        }

        const int z0 = a0 + c0;
        const int z1 = a1 + c1;

        // modrelu + 8-bit activation quantization (matches jnp.round half-even)
        int8_t* hb = (int8_t*)sh_h[nxt];
        {
            float zf = (float)z0 * (1.0f / 1024.0f);        // exact
            float m = fmaxf(fabsf(zf) + bc, 0.0f);
            int ni = (int)rintf(m * 128.0f);
            int nh = (z0 > 0) ? (ni > 127 ? 127 : ni)
                              : (z0 < 0 ? -(ni > 128 ? 128 : ni) : 0);
            hb[tid] = (int8_t)nh;
        }
        {
            float zf = (float)z1 * (1.0f / 1024.0f);
            float m = fmaxf(fabsf(zf) + bc, 0.0f);
            int ni = (int)rintf(m * 128.0f);
            int nh = (z1 > 0) ? (ni > 127 ? 127 : ni)
                              : (z1 < 0 ? -(ni > 128 ? 128 : ni) : 0);
            hb[256 + tid] = (int8_t)nh;
        }

        // Stage quantized x(t+1) into the next buffer
        if (tid < 128) {
            int q = clampi((int)rintf(xv * 128.0f), -128, 127);
            ((int8_t*)sh_x[nxt])[pr * 64 + pi] = (int8_t)q;
        }

        __syncthreads();
    }

    // Output head: h_last (in buffer (TT & 1) = 0) @ Wo_q^T, /1024 exact
    if (tid < 32) {
        const int o = tid & 15;
        const int r = tid >> 4;
        const uint32_t* hrow = sh_h[0][r];
        int acc = 0;
#pragma unroll
        for (int kw = 0; kw < 64; kw++)
            acc = __dp4a((int)hrow[kw], (int)g_WoP[o * 64 + kw], acc);
        out[(r0 + r) * NO + o] = (float)acc * (1.0f / 1024.0f);
    }
}

extern "C" void kernel_launch(void* const* d_in, const int* in_sizes, int n_in,
                              void* d_out, int out_size) {
    const float* inputs = (const float*)d_in[0];  // [256,1024,64]
    const float* Wi     = (const float*)d_in[1];  // [256,64]
    const float* Wr     = (const float*)d_in[2];  // [256,256]
    const float* Wo     = (const float*)d_in[3];  // [16,256]
    const float* b      = (const float*)d_in[4];  // [256]
    float* out = (float*)d_out;                   // [256,16]

    prep_kernel<<<1, 256>>>(Wi, Wr, Wo);
    qornn_kernel<<<128, 256>>>(inputs, b, out);
}

// round 4
// speedup vs baseline: 1.0470x; 1.0470x over previous
#include <cuda_runtime.h>
#include <cstdint>

// QORNN: B=256, T=1024, I=64, H=256, O=16
// Exact integer reformulation (bit-exact vs reference, rel_err 0.0 in R2):
//   x_q  = clip(rint(x*128), -128, 127)           (int8, scale 1/128)
//   Wi_q/Wr_q/Wo_q = clip(rint(W*8), -8, 7)       (int4-valued int8, scale 1/8)
//   z = (sum x_q*Wi_q + sum h_q*Wr_q) / 1024      (int32 accum, exact in fp32 grid)
//   m = relu(|z| + b); h_q = clip(rint(sign(z)*m*128), -128, 127)
//
// R3 change: 1 batch row per CTA, 256 CTAs, 2 CTAs/SM (independent barriers
// overlap each other's stalls). Regs capped at 128 via __launch_bounds__(256,2).

#define TT 1024
#define NB 256
#define HH 256
#define NI 64
#define NO 16

__device__ uint32_t g_WiP[HH * 16];   // packed int8 x4 per hidden unit
__device__ uint32_t g_WrP[HH * 64];
__device__ uint32_t g_WoP[NO * 64];

__device__ __forceinline__ int clampi(int v, int lo, int hi) {
    return v < lo ? lo : (v > hi ? hi : v);
}

__device__ __forceinline__ uint32_t pack4(const float* p, float scale, int lo, int hi) {
    uint32_t w = 0;
#pragma unroll
    for (int j = 0; j < 4; j++) {
        int q = clampi((int)rintf(p[j] * scale), lo, hi);
        w |= ((uint32_t)(uint8_t)(int8_t)q) << (8 * j);
    }
    return w;
}

__global__ void prep_kernel(const float* __restrict__ Wi,
                            const float* __restrict__ Wr,
                            const float* __restrict__ Wo) {
    int c = threadIdx.x;  // 0..255
    for (int kw = 0; kw < 64; kw++)
        g_WrP[c * 64 + kw] = pack4(Wr + c * HH + kw * 4, 8.0f, -8, 7);
    for (int kw = 0; kw < 16; kw++)
        g_WiP[c * 16 + kw] = pack4(Wi + c * NI + kw * 4, 8.0f, -8, 7);
    if (c < NO) {
        for (int kw = 0; kw < 64; kw++)
            g_WoP[c * 64 + kw] = pack4(Wo + c * HH + kw * 4, 8.0f, -8, 7);
    }
}

// One CTA = ONE batch row for all T steps; 2 CTAs co-resident per SM.
// Thread c owns hidden unit c; Wr/Wi rows in registers; h ping-pongs in SMEM.
__global__ __launch_bounds__(256, 2)
void qornn_kernel(const float* __restrict__ x,
                  const float* __restrict__ b,
                  float* __restrict__ out) {
    __shared__ uint32_t sh_h[2][64];   // [buf][kword] : 256 int8
    __shared__ uint32_t sh_x[2][16];   // [buf][kword] : 64 int8

    const int tid = threadIdx.x;
    const int r = blockIdx.x;          // batch row

    // Register-resident weights for this thread's hidden unit
    uint32_t wr[64];
#pragma unroll
    for (int kw = 0; kw < 64; kw++) wr[kw] = g_WrP[tid * 64 + kw];
    uint32_t wi[16];
#pragma unroll
    for (int kw = 0; kw < 16; kw++) wi[kw] = g_WiP[tid * 16 + kw];
    const float bc = b[tid];

    // h0 = 0 for both buffers (128 words)
    if (tid < 128) ((uint32_t*)sh_h)[tid] = 0u;

    // Pre-quantize x(t=0) into sh_x buffer 0
    const float* xrow = x + (size_t)r * (TT * NI);
    if (tid < NI) {
        int q = clampi((int)rintf(xrow[tid] * 128.0f), -128, 127);
        ((int8_t*)sh_x[0])[tid] = (int8_t)q;
    }
    __syncthreads();

    for (int t = 0; t < TT; t++) {
        const int cur = t & 1;
        const int nxt = cur ^ 1;

        // Prefetch x(t+1) early; global latency hidden under the dp4a block
        float xv = 0.0f;
        if (tid < NI) {
            int tn = (t + 1 < TT) ? (t + 1) : (TT - 1);
            xv = xrow[(size_t)tn * NI + tid];
        }

        // 4 interleaved accumulator chains (ILP >= lat/rt)
        int s0 = 0, s1 = 0, s2 = 0, s3 = 0;

        const uint4* xw = (const uint4*)sh_x[cur];
#pragma unroll
        for (int k = 0; k < 4; k++) {
            uint4 v = xw[k];
            s0 = __dp4a((int)v.x, (int)wi[4 * k + 0], s0);
            s1 = __dp4a((int)v.y, (int)wi[4 * k + 1], s1);
            s2 = __dp4a((int)v.z, (int)wi[4 * k + 2], s2);
            s3 = __dp4a((int)v.w, (int)wi[4 * k + 3], s3);
        }

        const uint4* hw = (const uint4*)sh_h[cur];
#pragma unroll
        for (int k = 0; k < 16; k++) {
            uint4 v = hw[k];
            s0 = __dp4a((int)v.x, (int)wr[4 * k + 0], s0);
            s1 = __dp4a((int)v.y, (int)wr[4 * k + 1], s1);
            s2 = __dp4a((int)v.z, (int)wr[4 * k + 2], s2);
            s3 = __dp4a((int)v.w, (int)wr[4 * k + 3], s3);
        }

        const int z = (s0 + s1) + (s2 + s3);

        // modrelu + 8-bit activation quantization (matches jnp.round half-even)
        {
            float zf = (float)z * (1.0f / 1024.0f);        // exact
            float m = fmaxf(fabsf(zf) + bc, 0.0f);
            int ni = (int)rintf(m * 128.0f);
            int nh = (z > 0) ? (ni > 127 ? 127 : ni)
                             : (z < 0 ? -(ni > 128 ? 128 : ni) : 0);
            ((int8_t*)sh_h[nxt])[tid] = (int8_t)nh;
        }

        // Stage quantized x(t+1) into the next buffer
        if (tid < NI) {
            int q = clampi((int)rintf(xv * 128.0f), -128, 127);
            ((int8_t*)sh_x[nxt])[tid] = (int8_t)q;
        }

        __syncthreads();
    }

    // Output head: h_last lives in buffer 0 after t=1023 (nxt of cur=1)
    if (tid < NO) {
        const uint32_t* hrow = sh_h[0];
        int acc = 0;
#pragma unroll
        for (int kw = 0; kw < 64; kw++)
            acc = __dp4a((int)hrow[kw], (int)g_WoP[tid * 64 + kw], acc);
        out[r * NO + tid] = (float)acc * (1.0f / 1024.0f);
    }
}

extern "C" void kernel_launch(void* const* d_in, const int* in_sizes, int n_in,
                              void* d_out, int out_size) {
    const float* inputs = (const float*)d_in[0];  // [256,1024,64]
    const float* Wi     = (const float*)d_in[1];  // [256,64]
    const float* Wr     = (const float*)d_in[2];  // [256,256]
    const float* Wo     = (const float*)d_in[3];  // [16,256]
    const float* b      = (const float*)d_in[4];  // [256]
    float* out = (float*)d_out;                   // [256,16]

    prep_kernel<<<1, 256>>>(Wi, Wr, Wo);
    qornn_kernel<<<NB, 256>>>(inputs, b, out);
}